// round 17
// baseline (speedup 1.0000x reference)
#include <cuda_runtime.h>
#include <cuda_fp16.h>
#include <math.h>
#include <stdint.h>

#define NB     4096
#define NROWS  8192
#define DDIM   128
#define NTILE  64          // 8192 / 128
#define NCTA   2080        // NTILE*(NTILE+1)/2 upper-triangle tiles
#define E2LOG2 2.885390081777927f   // 2 * log2(e)
#define SQS    1.698643603f          // sqrt(2 * log2(e))

// ---------------- static scratch (no allocations allowed) ----------------
__device__ uint8_t g8s[NROWS * DDIM];   // e4m3 reps scaled by sqrt(2*log2 e)
__device__ float   g_rowsum[NROWS];
__device__ float   g_pos[NROWS];
__device__ float   g_self[NROWS];
__device__ unsigned int g_count;

// ---------------- helpers ----------------
__device__ __forceinline__ uint32_t smem_u32(const void* p) {
    uint32_t a;
    asm("{ .reg .u64 t; cvta.to.shared.u64 t, %1; cvt.u32.u64 %0, t; }"
        : "=r"(a) : "l"(p));
    return a;
}
__device__ __forceinline__ void ldsm4(uint32_t* r, uint32_t addr) {
    asm volatile("ldmatrix.sync.aligned.m8n8.x4.shared.b16 {%0,%1,%2,%3}, [%4];"
                 : "=r"(r[0]), "=r"(r[1]), "=r"(r[2]), "=r"(r[3]) : "r"(addr));
}
// fp8 e4m3 MMA, f16 accumulate (acc = 2x f16x2)
__device__ __forceinline__ void mma_f8h(uint32_t* d, const uint32_t* a,
                                        uint32_t b0, uint32_t b1) {
    asm volatile("mma.sync.aligned.m16n8k32.row.col.f16.e4m3.e4m3.f16 "
                 "{%0,%1}, {%2,%3,%4,%5}, {%6,%7}, {%0,%1};"
                 : "+r"(d[0]), "+r"(d[1])
                 : "r"(a[0]), "r"(a[1]), "r"(a[2]), "r"(a[3]), "r"(b0), "r"(b1));
}
__device__ __forceinline__ uint32_t hadd2(uint32_t a, uint32_t b) {
    uint32_t o; asm("add.rn.f16x2 %0, %1, %2;" : "=r"(o) : "r"(a), "r"(b)); return o;
}
__device__ __forceinline__ uint32_t hex2(uint32_t a) {
    uint32_t o; asm("ex2.approx.f16x2 %0, %1;" : "=r"(o) : "r"(a)); return o;
}
__device__ __forceinline__ float2 h2f2(uint32_t h) {
    __half2 v = *reinterpret_cast<__half2*>(&h);
    return __half22float2(v);
}
// pack 4 f32 -> 4 e4m3 bytes (byte0 = x)
__device__ __forceinline__ uint32_t pack_e4m3x4(float x, float y, float z, float w) {
    uint16_t lo, hi;
    asm("cvt.rn.satfinite.e4m3x2.f32 %0, %1, %2;" : "=h"(lo) : "f"(y), "f"(x));
    asm("cvt.rn.satfinite.e4m3x2.f32 %0, %1, %2;" : "=h"(hi) : "f"(w), "f"(z));
    return (uint32_t)lo | ((uint32_t)hi << 16);
}
__device__ __forceinline__ void cp16(uint32_t dst, const void* src) {
    asm volatile("cp.async.cg.shared.global [%0], [%1], 16;"
                 :: "r"(dst), "l"(src) : "memory");
}
#define CP_COMMIT() asm volatile("cp.async.commit_group;" ::: "memory")
#define CP_WAIT0()  asm volatile("cp.async.wait_group 0;" ::: "memory")

// smem: 128-row A + 128-row B fp8 tiles only, pitch 144 B (9x16B, conflict-free)
#define PITCH    144
#define SM_A     0
#define SM_B     (128 * PITCH)
#define SMEM_SZ  (256 * PITCH)

// ---------------- K1: normalize pair + sqrt-scaled e4m3 + pos/self ----------------
__global__ void __launch_bounds__(256) k_norm(const float* __restrict__ p1,
                                              const float* __restrict__ p2) {
    int gw = (blockIdx.x * blockDim.x + threadIdx.x) >> 5;   // pair index 0..NB-1
    int lane = threadIdx.x & 31;
    if (gw >= NB) return;
    if (gw == 0 && lane == 0) g_count = 0;
    float4 v1 = *(const float4*)(p1 + (size_t)gw * DDIM + lane * 4);
    float4 v2 = *(const float4*)(p2 + (size_t)gw * DDIM + lane * 4);
    float ss1 = v1.x*v1.x + v1.y*v1.y + v1.z*v1.z + v1.w*v1.w;
    float ss2 = v2.x*v2.x + v2.y*v2.y + v2.z*v2.z + v2.w*v2.w;
    float cx  = v1.x*v2.x + v1.y*v2.y + v1.z*v2.z + v1.w*v2.w;
#pragma unroll
    for (int o = 16; o; o >>= 1) {
        ss1 += __shfl_xor_sync(0xffffffffu, ss1, o);
        ss2 += __shfl_xor_sync(0xffffffffu, ss2, o);
        cx  += __shfl_xor_sync(0xffffffffu, cx,  o);
    }
    float inv1 = rsqrtf(fmaxf(ss1, 1e-24f));
    float inv2 = rsqrtf(fmaxf(ss2, 1e-24f));
    float sc1 = inv1 * SQS;
    float sc2 = inv2 * SQS;

    *(uint32_t*)(g8s + (size_t)gw * DDIM + lane * 4) =
        pack_e4m3x4(v1.x*sc1, v1.y*sc1, v1.z*sc1, v1.w*sc1);
    *(uint32_t*)(g8s + (size_t)(gw + NB) * DDIM + lane * 4) =
        pack_e4m3x4(v2.x*sc2, v2.y*sc2, v2.z*sc2, v2.w*sc2);

    if (lane == 0) {
        float pos = cx * inv1 * inv2;
        g_pos[gw] = pos;            g_pos[gw + NB] = pos;
        g_self[gw] = ss1 * inv1 * inv1;
        g_self[gw + NB] = ss2 * inv2 * inv2;
        g_rowsum[gw] = 0.0f;        g_rowsum[gw + NB] = 0.0f;
    }
}

// ---------------- K2: FP8 MMA sim-GEMM + last-CTA final reduction ----------------
extern __shared__ char smem_raw[];

__global__ void __launch_bounds__(256, 3) k_gemm(float* __restrict__ out) {
    const int tid  = threadIdx.x;
    const int wid  = tid >> 5;
    const int lane = tid & 31;

    // decode upper-triangle tile (bi <= bj) from linear blockIdx
    int t = blockIdx.x;
    int bi = (int)(64.5f - sqrtf(64.5f * 64.5f - 2.0f * (float)t));
    while (bi * NTILE - (bi * (bi - 1)) / 2 > t) --bi;
    while ((bi + 1) * NTILE - ((bi + 1) * bi) / 2 <= t) ++bi;
    const int bj = bi + (t - (bi * NTILE - (bi * (bi - 1)) / 2));
    const bool diag = (bi == bj);
    const int r0 = bi * 128;
    const int c0 = bj * 128;

    const uint32_t sb = smem_u32(smem_raw);

    // async load A (rows r0..+127) + B (rows c0..+127), same scaled array
#pragma unroll
    for (int it = 0; it < 8; ++it) {
        int idx = tid + it * 256;
        int row = idx >> 3;
        int seg = idx & 7;
        int grow = (row < 128) ? r0 + row : c0 + (row - 128);
        cp16(sb + (uint32_t)(row * PITCH + seg * 16),
             g8s + (size_t)grow * DDIM + seg * 16);
    }
    CP_COMMIT();
    CP_WAIT0();
    __syncthreads();

    const int wm = wid >> 2;          // 0..1 -> rows 64*wm
    const int wn = wid & 3;           // 0..3 -> cols 32*wn

    const uint32_t a_base = sb +
        (uint32_t)((64 * wm + (lane & 15)) * PITCH + (lane >> 4) * 16);
    const int brow = 32 * wn + (lane & 7) + ((lane >> 4) << 3);
    const uint32_t b_base = sb + SM_B +
        (uint32_t)(brow * PITCH + ((lane >> 3) & 1) * 16);

    uint32_t acc[4][4][2];            // f16x2 accumulators (= 2*log2e*sim)
#pragma unroll
    for (int mi = 0; mi < 4; ++mi)
#pragma unroll
        for (int nj = 0; nj < 4; ++nj) { acc[mi][nj][0] = 0u; acc[mi][nj][1] = 0u; }

#pragma unroll
    for (int kk = 0; kk < 4; ++kk) {           // 4 k-blocks of 32
        uint32_t b0[4], b1[4];
        ldsm4(b0, b_base + kk * 32);           // cols 0-15 of this warp's 32
        ldsm4(b1, b_base + 16 * PITCH + kk * 32);  // cols 16-31
#pragma unroll
        for (int mi = 0; mi < 4; ++mi) {
            uint32_t a[4];
            ldsm4(a, a_base + kk * 32 + mi * 16 * PITCH);
            mma_f8h(acc[mi][0], a, b0[0], b0[1]);
            mma_f8h(acc[mi][1], a, b0[2], b0[3]);
            mma_f8h(acc[mi][2], a, b1[0], b1[1]);
            mma_f8h(acc[mi][3], a, b1[2], b1[3]);
        }
    }

    // exp: accs pre-scaled -> bare ex2.approx.f16x2 (2 exps per MUFU op)
#pragma unroll
    for (int mi = 0; mi < 4; ++mi)
#pragma unroll
        for (int nj = 0; nj < 4; ++nj) {
            acc[mi][nj][0] = hex2(acc[mi][nj][0]);
            acc[mi][nj][1] = hex2(acc[mi][nj][1]);
        }

    // row partial sums: packed f16x2 quad-reduce, leader converts + REDG
    const int rbase = r0 + 64 * wm + (lane >> 2);
#pragma unroll
    for (int mi = 0; mi < 4; ++mi) {
        uint32_t hlo = hadd2(hadd2(acc[mi][0][0], acc[mi][1][0]),
                             hadd2(acc[mi][2][0], acc[mi][3][0]));
        uint32_t hhi = hadd2(hadd2(acc[mi][0][1], acc[mi][1][1]),
                             hadd2(acc[mi][2][1], acc[mi][3][1]));
        hlo = hadd2(hlo, __shfl_xor_sync(0xffffffffu, hlo, 1));
        hlo = hadd2(hlo, __shfl_xor_sync(0xffffffffu, hlo, 2));
        hhi = hadd2(hhi, __shfl_xor_sync(0xffffffffu, hhi, 1));
        hhi = hadd2(hhi, __shfl_xor_sync(0xffffffffu, hhi, 2));
        if ((lane & 3) == 0) {
            float2 flo = h2f2(hlo), fhi = h2f2(hhi);
            atomicAdd(&g_rowsum[rbase + 16 * mi],     flo.x + flo.y);
            atomicAdd(&g_rowsum[rbase + 16 * mi + 8], fhi.x + fhi.y);
        }
    }

    // column partial sums: packed f16x2 octet-reduce, lanes 0-3 REDG
    if (!diag) {
#pragma unroll
        for (int nj = 0; nj < 4; ++nj) {
            uint32_t v2 = hadd2(hadd2(acc[0][nj][0], acc[0][nj][1]),
                                hadd2(acc[1][nj][0], acc[1][nj][1]));
            v2 = hadd2(v2, hadd2(hadd2(acc[2][nj][0], acc[2][nj][1]),
                                 hadd2(acc[3][nj][0], acc[3][nj][1])));
            v2 = hadd2(v2, __shfl_down_sync(0xffffffffu, v2, 16));
            v2 = hadd2(v2, __shfl_down_sync(0xffffffffu, v2, 8));
            v2 = hadd2(v2, __shfl_down_sync(0xffffffffu, v2, 4));
            if (lane < 4) {
                float2 f = h2f2(v2);
                atomicAdd(&g_rowsum[c0 + 32 * wn + 8 * nj + lane * 2],     f.x);
                atomicAdd(&g_rowsum[c0 + 32 * wn + 8 * nj + lane * 2 + 1], f.y);
            }
        }
    }

    // ---- last-CTA final reduction (replaces a separate kernel) ----
    __shared__ int s_last;
    __shared__ float red[256];
    __syncthreads();                       // all this CTA's REDG issued+visible to tid0
    if (tid == 0) {
        __threadfence();                   // make them device-visible before counting
        unsigned int old = atomicAdd(&g_count, 1u);
        s_last = (old == NCTA - 1u);
    }
    __syncthreads();
    if (s_last) {
        __threadfence();
        float local = 0.0f;
        for (int r = tid; r < NROWS; r += 256) {
            float den = g_rowsum[r] - exp2f(E2LOG2 * g_self[r]);
            local += __logf(den) - 2.0f * g_pos[r];
        }
        red[tid] = local;
        __syncthreads();
#pragma unroll
        for (int o = 128; o; o >>= 1) {
            if (tid < o) red[tid] += red[tid + o];
            __syncthreads();
        }
        if (tid == 0) out[0] = red[0] * (1.0f / (float)NROWS);
    }
}

// ---------------- launcher ----------------
extern "C" void kernel_launch(void* const* d_in, const int* in_sizes, int n_in,
                              void* d_out, int out_size) {
    const float* p1 = (const float*)d_in[0];
    const float* p2 = (const float*)d_in[1];
    float* out = (float*)d_out;

    cudaFuncSetAttribute(k_gemm, cudaFuncAttributeMaxDynamicSharedMemorySize, SMEM_SZ);

    k_norm<<<NB / 8, 256>>>(p1, p2);
    k_gemm<<<NCTA, 256, SMEM_SZ>>>(out);
}